// round 10
// baseline (speedup 1.0000x reference)
#include <cuda_runtime.h>
#include <math.h>
#include <stdint.h>

#define NEDGE 320000
#define NUN   10000
#define NVN   10000
#define FIN   128

// ---------------- scratch (static device globals; no allocation) ------------
__device__ float    g_pu[NUN * 256];
__device__ float    g_pv[NVN * 256];
__device__ float    g_att_u[NUN * 256];
__device__ float    g_att_v[NVN * 256];
__device__ float    g_agg_u[NUN * 256];   // UNNORMALIZED exp-weighted sums
__device__ float    g_agg_v[NVN * 256];
__device__ float    g_s_bwd[NUN];         // segment sums of exp
__device__ float    g_s_fwd[NVN];

__device__ __forceinline__ float f2tf32(float f) {
    uint32_t r;
    asm("cvt.rna.tf32.f32 %0, %1;" : "=r"(r) : "f"(f));
    return __uint_as_float(r);
}
__device__ __forceinline__ void mma_tf32(float* d, const uint32_t* a,
                                         uint32_t b0, uint32_t b1) {
    asm volatile(
        "mma.sync.aligned.m16n8k8.row.col.f32.tf32.tf32.f32 "
        "{%0,%1,%2,%3}, {%4,%5,%6,%7}, {%8,%9}, {%0,%1,%2,%3};"
        : "+f"(d[0]), "+f"(d[1]), "+f"(d[2]), "+f"(d[3])
        : "r"(a[0]), "r"(a[1]), "r"(a[2]), "r"(a[3]), "r"(b0), "r"(b1));
}
__device__ __forceinline__ void red4(float* p, float4 v) {
    asm volatile("red.global.add.v4.f32 [%0], {%1,%2,%3,%4};"
                 :: "l"(p), "f"(v.x), "f"(v.y), "f"(v.z), "f"(v.w) : "memory");
}

// ---------------- init ------------------------------------------------------
__global__ void init_kernel() {
    int i = blockIdx.x * blockDim.x + threadIdx.x;
    if (i < NUN * 256) g_agg_u[i] = 0.f;
    if (i < NVN * 256) g_agg_v[i] = 0.f;
    if (i < NUN) g_s_bwd[i] = 0.f;
    if (i < NVN) g_s_fwd[i] = 0.f;
}

// ============ he GEMM: BM=128, BN=256, 256 threads, synchronous =============
// he = relu(e_feat @ We + be + g_pu[src] + g_pv[dst]);  M % 128 == 0
// Same proven inner structure as tf32gemm: cvt at STS, fragments raw from smem.
#define HE_ASTR 36
#define HE_BSTR 264
#define HE_ABUF (128 * HE_ASTR)          // 4608 floats
#define HE_SMEM ((HE_ABUF + 32 * HE_BSTR) * 4)   // 52224 bytes

__global__ __launch_bounds__(256)
void he_gemm(const float* __restrict__ A, const float* __restrict__ W,
             const float* __restrict__ bias, float* __restrict__ C,
             const int* __restrict__ src, const int* __restrict__ dst) {
    extern __shared__ float sh[];
    float* As = sh;
    float* Bs = sh + HE_ABUF;

    const int t    = threadIdx.x;
    const int warp = t >> 5;
    const int lane = t & 31;
    const int qr   = lane >> 2;
    const int qc   = lane & 3;
    const int wm   = warp >> 2;           // 0..1
    const int wn   = warp & 3;            // 0..3
    const int row0 = blockIdx.x * 128;

    float acc[4][8][4];
#pragma unroll
    for (int i = 0; i < 4; i++)
#pragma unroll
        for (int j = 0; j < 8; j++)
#pragma unroll
            for (int q = 0; q < 4; q++) acc[i][j][q] = 0.f;

    for (int k0 = 0; k0 < 128; k0 += 32) {
        // A: 128 rows x 8 f4-slots, 4 per thread (cvt at STS)
#pragma unroll
        for (int p = 0; p < 4; p++) {
            int slot = t + p * 256;
            int r = slot >> 3, c = slot & 7;
            float4 v = *(const float4*)&A[(size_t)(row0 + r) * 128 + k0 + c * 4];
            float* s = &As[r * HE_ASTR + c * 4];
            s[0] = f2tf32(v.x); s[1] = f2tf32(v.y);
            s[2] = f2tf32(v.z); s[3] = f2tf32(v.w);
        }
        // B: 32 rows x 64 f4-slots, 8 per thread
#pragma unroll
        for (int p = 0; p < 8; p++) {
            int slot = t + p * 256;
            int kr = slot >> 6, c = slot & 63;
            float4 v = *(const float4*)&W[(size_t)(k0 + kr) * 256 + c * 4];
            float* s = &Bs[kr * HE_BSTR + c * 4];
            s[0] = f2tf32(v.x); s[1] = f2tf32(v.y);
            s[2] = f2tf32(v.z); s[3] = f2tf32(v.w);
        }
        __syncthreads();
#pragma unroll
        for (int kk = 0; kk < 32; kk += 8) {
            uint32_t a[4][4];
#pragma unroll
            for (int i = 0; i < 4; i++) {
                const float* base = &As[(wm * 64 + 16 * i + qr) * HE_ASTR + kk + qc];
                a[i][0] = __float_as_uint(base[0]);
                a[i][1] = __float_as_uint(base[8 * HE_ASTR]);
                a[i][2] = __float_as_uint(base[4]);
                a[i][3] = __float_as_uint(base[8 * HE_ASTR + 4]);
            }
#pragma unroll
            for (int j = 0; j < 8; j++) {
                int n = wn * 64 + j * 8 + qr;
                uint32_t b0 = __float_as_uint(Bs[(kk + qc) * HE_BSTR + n]);
                uint32_t b1 = __float_as_uint(Bs[(kk + 4 + qc) * HE_BSTR + n]);
#pragma unroll
                for (int i = 0; i < 4; i++) mma_tf32(acc[i][j], a[i], b0, b1);
            }
        }
        __syncthreads();
    }

    // epilogue: + bias + pu[src] + pv[dst], relu
#pragma unroll
    for (int i = 0; i < 4; i++) {
#pragma unroll
        for (int h = 0; h < 2; h++) {
            int gr = row0 + wm * 64 + 16 * i + qr + 8 * h;
            int s_ = src[gr], d_ = dst[gr];
            const float* pu = &g_pu[0] + (size_t)s_ * 256;
            const float* pv = &g_pv[0] + (size_t)d_ * 256;
#pragma unroll
            for (int j = 0; j < 8; j++) {
                int col = wn * 64 + j * 8 + 2 * qc;
                float x0 = acc[i][j][2 * h]     + bias[col]     + pu[col]     + pv[col];
                float x1 = acc[i][j][2 * h + 1] + bias[col + 1] + pu[col + 1] + pv[col + 1];
                *(float2*)&C[(size_t)gr * 256 + col] =
                    make_float2(fmaxf(x0, 0.f), fmaxf(x1, 0.f));
            }
        }
    }
}

// =====================  tf32 tensor-core GEMM (R3/R5-proven body)  ==========
// MODE 0: plain   MODE 2: relu   MODE 4: relu, A row scaled by 1/rowScale[r]
template <int BN, int KTOT, int MODE>
__launch_bounds__(128)
__global__ void tf32gemm(const float* __restrict__ A,
                         const float* __restrict__ W,
                         const float* __restrict__ bias,
                         float* __restrict__ C, int ldc, int col_off, int M,
                         const float* __restrict__ rowScale) {
    constexpr int KC = 32;
    constexpr int WN = BN / 4;
    constexpr int NT = WN / 8;
    constexpr int ASTR = KC + 4;
    constexpr int BSTR = BN + 8;
    __shared__ float As[64 * ASTR];
    __shared__ float Bs[KC * BSTR];

    const int t    = threadIdx.x;
    const int warp = t >> 5;
    const int lane = t & 31;
    const int qr   = lane >> 2;
    const int qc   = lane & 3;
    const int row0 = blockIdx.x * 64;

    float acc[4][NT][4];
#pragma unroll
    for (int i = 0; i < 4; i++)
#pragma unroll
        for (int j = 0; j < NT; j++)
#pragma unroll
            for (int q = 0; q < 4; q++) acc[i][j][q] = 0.f;

    for (int k0 = 0; k0 < KTOT; k0 += KC) {
#pragma unroll
        for (int p = 0; p < 4; p++) {
            int slot = t + p * 128;
            int r = slot >> 3, c = slot & 7;
            float4 v = make_float4(0.f, 0.f, 0.f, 0.f);
            int gr = row0 + r;
            if (gr < M) {
                v = *(const float4*)&A[(size_t)gr * KTOT + k0 + c * 4];
                if (MODE == 4) {
                    float sden = rowScale[gr];
                    float rs = sden > 0.f ? __fdividef(1.f, sden) : 0.f;
                    v.x *= rs; v.y *= rs; v.z *= rs; v.w *= rs;
                }
            }
            float* s = &As[r * ASTR + c * 4];
            s[0] = f2tf32(v.x); s[1] = f2tf32(v.y);
            s[2] = f2tf32(v.z); s[3] = f2tf32(v.w);
        }
#pragma unroll
        for (int p = 0; p < KC * BN / 512; p++) {
            int slot = t + p * 128;
            int kr = slot / (BN / 4);
            int c  = slot % (BN / 4);
            float4 v = *(const float4*)&W[(size_t)(k0 + kr) * BN + c * 4];
            float* s = &Bs[kr * BSTR + c * 4];
            s[0] = f2tf32(v.x); s[1] = f2tf32(v.y);
            s[2] = f2tf32(v.z); s[3] = f2tf32(v.w);
        }
        __syncthreads();
#pragma unroll
        for (int kk = 0; kk < KC; kk += 8) {
            uint32_t a[4][4];
#pragma unroll
            for (int i = 0; i < 4; i++) {
                const float* base = &As[(16 * i + qr) * ASTR + kk + qc];
                a[i][0] = __float_as_uint(base[0]);
                a[i][1] = __float_as_uint(base[8 * ASTR]);
                a[i][2] = __float_as_uint(base[4]);
                a[i][3] = __float_as_uint(base[8 * ASTR + 4]);
            }
#pragma unroll
            for (int j = 0; j < NT; j++) {
                int n = warp * WN + j * 8 + qr;
                uint32_t b0 = __float_as_uint(Bs[(kk + qc) * BSTR + n]);
                uint32_t b1 = __float_as_uint(Bs[(kk + 4 + qc) * BSTR + n]);
#pragma unroll
                for (int i = 0; i < 4; i++) mma_tf32(acc[i][j], a[i], b0, b1);
            }
        }
        __syncthreads();
    }

#pragma unroll
    for (int i = 0; i < 4; i++) {
#pragma unroll
        for (int h = 0; h < 2; h++) {
            int gr = row0 + 16 * i + qr + 8 * h;
            if (gr >= M) continue;
#pragma unroll
            for (int j = 0; j < NT; j++) {
                int col = warp * WN + j * 8 + 2 * qc;
                float x0 = acc[i][j][2 * h]     + bias[col];
                float x1 = acc[i][j][2 * h + 1] + bias[col + 1];
                if (MODE >= 2) { x0 = fmaxf(x0, 0.f); x1 = fmaxf(x1, 0.f); }
                *(float2*)&C[(size_t)gr * ldc + col_off + col] = make_float2(x0, x1);
            }
        }
    }
}

// ---------------- fp32 SIMT GEMM (attention projections) --------------------
__launch_bounds__(128)
__global__ void gemm64_f32(const float* __restrict__ A, int K,
                           const float* __restrict__ W, int Ntot,
                           const float* __restrict__ bias,
                           float* __restrict__ C, int ldc, int M) {
    __shared__ __align__(16) float As[16][64];
    __shared__ __align__(16) float Ws[16][64];
    const int t  = threadIdx.x;
    const int ty = t >> 3;
    const int tx = t & 7;
    const int row0 = blockIdx.y * 64;
    const int n0   = blockIdx.x * 64;

    float acc[4][8];
#pragma unroll
    for (int i = 0; i < 4; i++)
#pragma unroll
        for (int j = 0; j < 8; j++) acc[i][j] = 0.f;

    for (int k0 = 0; k0 < K; k0 += 16) {
#pragma unroll
        for (int j = 0; j < 2; j++) {
            int idx = t * 2 + j;
            int r  = idx >> 2;
            int c4 = idx & 3;
            float4 v = make_float4(0.f, 0.f, 0.f, 0.f);
            int gr = row0 + r;
            if (gr < M) v = *(const float4*)&A[(size_t)gr * K + k0 + c4 * 4];
            As[c4 * 4 + 0][r] = v.x;
            As[c4 * 4 + 1][r] = v.y;
            As[c4 * 4 + 2][r] = v.z;
            As[c4 * 4 + 3][r] = v.w;
        }
#pragma unroll
        for (int j = 0; j < 2; j++) {
            int idx = t * 2 + j;
            int kr  = idx >> 4;
            int c4  = idx & 15;
            *(float4*)&Ws[kr][c4 * 4] =
                *(const float4*)&W[(size_t)(k0 + kr) * Ntot + n0 + c4 * 4];
        }
        __syncthreads();
#pragma unroll
        for (int kk = 0; kk < 16; kk++) {
            float4 a  = *(const float4*)&As[kk][ty * 4];
            float4 b0 = *(const float4*)&Ws[kk][tx * 8];
            float4 b1 = *(const float4*)&Ws[kk][tx * 8 + 4];
            float av[4] = {a.x, a.y, a.z, a.w};
            float bv[8] = {b0.x, b0.y, b0.z, b0.w, b1.x, b1.y, b1.z, b1.w};
#pragma unroll
            for (int i = 0; i < 4; i++)
#pragma unroll
                for (int j = 0; j < 8; j++) acc[i][j] = fmaf(av[i], bv[j], acc[i][j]);
        }
        __syncthreads();
    }

#pragma unroll
    for (int i = 0; i < 4; i++) {
        int r = row0 + ty * 4 + i;
        if (r >= M) continue;
#pragma unroll
        for (int j = 0; j < 8; j++) {
            int n = n0 + tx * 8 + j;
            C[(size_t)r * ldc + n] = acc[i][j] + bias[n];
        }
    }
}

// ===== fused edge pass: logit -> exp (no max shift) -> weighted scatter =====
__global__ void edge_kernel(const float* __restrict__ e_feat,
                            const float* __restrict__ u_feat,
                            const float* __restrict__ v_feat,
                            const int* __restrict__ src,
                            const int* __restrict__ dst) {
    int e = blockIdx.x * 8 + (threadIdx.x >> 5);
    int lane = threadIdx.x & 31;
    int c = lane * 4;
    int s = src[e], d = dst[e];
    float4 ev = *(const float4*)&e_feat[(size_t)e * FIN + c];
    float4 uv = *(const float4*)&u_feat[(size_t)s * FIN + c];
    float4 vv = *(const float4*)&v_feat[(size_t)d * FIN + c];
    float4 au0 = *(const float4*)&g_att_u[(size_t)s * 256 + c];
    float4 au1 = *(const float4*)&g_att_u[(size_t)s * 256 + 128 + c];
    float4 av0 = *(const float4*)&g_att_v[(size_t)d * 256 + c];
    float4 av1 = *(const float4*)&g_att_v[(size_t)d * 256 + 128 + c];
    float sb = vv.x * au0.x + vv.y * au0.y + vv.z * au0.z + vv.w * au0.w
             + ev.x * au1.x + ev.y * au1.y + ev.z * au1.z + ev.w * au1.w;
    float sf = uv.x * av0.x + uv.y * av0.y + uv.z * av0.z + uv.w * av0.w
             + ev.x * av1.x + ev.y * av1.y + ev.z * av1.z + ev.w * av1.w;
#pragma unroll
    for (int o = 16; o; o >>= 1) {
        sb += __shfl_xor_sync(0xFFFFFFFFu, sb, o);
        sf += __shfl_xor_sync(0xFFFFFFFFu, sf, o);
    }
    float wb = expf(sb);
    float wf = expf(sf);
    float* agu = g_agg_u + (size_t)s * 256;
    float* agv = g_agg_v + (size_t)d * 256;
    red4(&agu[c],       make_float4(wb * vv.x, wb * vv.y, wb * vv.z, wb * vv.w));
    red4(&agu[c + 128], make_float4(wb * ev.x, wb * ev.y, wb * ev.z, wb * ev.w));
    red4(&agv[c],       make_float4(wf * uv.x, wf * uv.y, wf * uv.z, wf * uv.w));
    red4(&agv[c + 128], make_float4(wf * ev.x, wf * ev.y, wf * ev.z, wf * ev.w));
    if (lane == 0) {
        atomicAdd(&g_s_bwd[s], wb);
        atomicAdd(&g_s_fwd[d], wf);
    }
}

// ---------------- launch: forked-stream CUDA-graph DAG -----------------------
extern "C" void kernel_launch(void* const* d_in, const int* in_sizes, int n_in,
                              void* d_out, int out_size) {
    const float* e_feat = (const float*)d_in[0];
    const float* u_feat = (const float*)d_in[1];
    const float* v_feat = (const float*)d_in[2];
    const int*   src    = (const int*)d_in[3];
    const int*   dst    = (const int*)d_in[4];
    const float* We  = (const float*)d_in[5];  const float* be  = (const float*)d_in[6];
    const float* Wu  = (const float*)d_in[7];  const float* bu  = (const float*)d_in[8];
    const float* Wv  = (const float*)d_in[9];  const float* bv  = (const float*)d_in[10];
    const float* Wau = (const float*)d_in[11]; const float* bau = (const float*)d_in[12];
    const float* Wav = (const float*)d_in[13]; const float* bav = (const float*)d_in[14];
    const float* Wnu = (const float*)d_in[15]; const float* bnu = (const float*)d_in[16];
    const float* Wnv = (const float*)d_in[17]; const float* bnv = (const float*)d_in[18];
    const float* Vu  = (const float*)d_in[19]; const float* bVu = (const float*)d_in[20];
    const float* Vv  = (const float*)d_in[21]; const float* bVv = (const float*)d_in[22];

    float* out    = (float*)d_out;
    float* out_he = out;
    float* out_hu = out + (size_t)NEDGE * 256;
    float* out_hv = out_hu + (size_t)NUN * 256;

    float *pu, *pv, *au, *av, *aggu, *aggv, *sb, *sf;
    cudaGetSymbolAddress((void**)&pu,   g_pu);
    cudaGetSymbolAddress((void**)&pv,   g_pv);
    cudaGetSymbolAddress((void**)&au,   g_att_u);
    cudaGetSymbolAddress((void**)&av,   g_att_v);
    cudaGetSymbolAddress((void**)&aggu, g_agg_u);
    cudaGetSymbolAddress((void**)&aggv, g_agg_v);
    cudaGetSymbolAddress((void**)&sb,   g_s_bwd);
    cudaGetSymbolAddress((void**)&sf,   g_s_fwd);

    static cudaStream_t s1, s2, s3;
    static cudaEvent_t evRoot, evInit, evPP, evAgg, evSkip;
    static bool once = false;
    if (!once) {
        cudaStreamCreateWithFlags(&s1, cudaStreamNonBlocking);
        cudaStreamCreateWithFlags(&s2, cudaStreamNonBlocking);
        cudaStreamCreateWithFlags(&s3, cudaStreamNonBlocking);
        cudaEventCreateWithFlags(&evRoot, cudaEventDisableTiming);
        cudaEventCreateWithFlags(&evInit, cudaEventDisableTiming);
        cudaEventCreateWithFlags(&evPP,   cudaEventDisableTiming);
        cudaEventCreateWithFlags(&evAgg,  cudaEventDisableTiming);
        cudaEventCreateWithFlags(&evSkip, cudaEventDisableTiming);
        cudaFuncSetAttribute(he_gemm, cudaFuncAttributeMaxDynamicSharedMemorySize,
                             HE_SMEM);
        once = true;
    }

    const int MB = (NUN + 63) / 64;   // 157

    cudaEventRecord(evRoot, 0);

    // slot 1: init (main)
    init_kernel<<<(NUN * 256 + 255) / 256, 256>>>();
    cudaEventRecord(evInit, 0);

    // slots 2-3: pu / pv projections (s1)
    cudaStreamWaitEvent(s1, evRoot, 0);
    tf32gemm<256, 128, 0><<<MB, 128, 0, s1>>>(u_feat, Wu, bu, pu, 256, 0, NUN, nullptr);
    tf32gemm<256, 128, 0><<<MB, 128, 0, s1>>>(v_feat, Wv, bv, pv, 256, 0, NVN, nullptr);
    cudaEventRecord(evPP, s1);

    // slot 4: att_u (s2)
    cudaStreamWaitEvent(s2, evRoot, 0);
    gemm64_f32<<<dim3(4, MB), 128, 0, s2>>>(u_feat, 128, Wau, 256, bau, au, 256, NUN);

    // slot 5: he (main; waits pu/pv) — ncu -s 5 -c 1 lands HERE
    cudaStreamWaitEvent(0, evPP, 0);
    he_gemm<<<NEDGE / 128, 256, HE_SMEM>>>(e_feat, We, be, out_he, src, dst);

    // slot 6: att_v (s2), slot 7: fused edge pass (s2)
    gemm64_f32<<<dim3(4, MB), 128, 0, s2>>>(v_feat, 128, Wav, 256, bav, av, 256, NVN);
    cudaStreamWaitEvent(s2, evInit, 0);
    edge_kernel<<<NEDGE / 8, 256, 0, s2>>>(e_feat, u_feat, v_feat, src, dst);
    cudaEventRecord(evAgg, s2);

    // slots 8-9: skip halves of hu / hv (s3)
    cudaStreamWaitEvent(s3, evRoot, 0);
    tf32gemm<128, 128, 0><<<MB, 128, 0, s3>>>(u_feat, Vu, bVu, out_hu, 256, 0, NUN, nullptr);
    tf32gemm<128, 128, 0><<<MB, 128, 0, s3>>>(v_feat, Vv, bVv, out_hv, 256, 0, NVN, nullptr);
    cudaEventRecord(evSkip, s3);

    // slots 10-11: head GEMMs with fused 1/s normalization (main)
    cudaStreamWaitEvent(0, evAgg, 0);
    tf32gemm<128, 256, 4><<<MB, 128>>>(aggu, Wnu, bnu, out_hu, 256, 128, NUN, sb);
    tf32gemm<128, 256, 4><<<MB, 128>>>(aggv, Wnv, bnv, out_hv, 256, 128, NVN, sf);

    cudaStreamWaitEvent(0, evSkip, 0);
}

// round 11
// speedup vs baseline: 1.1454x; 1.1454x over previous
#include <cuda_runtime.h>
#include <math.h>
#include <stdint.h>

#define NEDGE 320000
#define NUN   10000
#define NVN   10000
#define FIN   128

// ---------------- scratch (static device globals; no allocation) ------------
__device__ float    g_pu[NUN * 256];
__device__ float    g_pv[NVN * 256];
__device__ float    g_att_u[NUN * 256];
__device__ float    g_att_v[NVN * 256];
__device__ float    g_agg_u[NUN * 256];   // UNNORMALIZED exp-weighted sums
__device__ float    g_agg_v[NVN * 256];
__device__ float    g_s_bwd[NUN];         // segment sums of exp
__device__ float    g_s_fwd[NVN];

__device__ __forceinline__ float f2tf32(float f) {
    uint32_t r;
    asm("cvt.rna.tf32.f32 %0, %1;" : "=r"(r) : "f"(f));
    return __uint_as_float(r);
}
__device__ __forceinline__ void mma_tf32(float* d, const uint32_t* a,
                                         uint32_t b0, uint32_t b1) {
    asm volatile(
        "mma.sync.aligned.m16n8k8.row.col.f32.tf32.tf32.f32 "
        "{%0,%1,%2,%3}, {%4,%5,%6,%7}, {%8,%9}, {%0,%1,%2,%3};"
        : "+f"(d[0]), "+f"(d[1]), "+f"(d[2]), "+f"(d[3])
        : "r"(a[0]), "r"(a[1]), "r"(a[2]), "r"(a[3]), "r"(b0), "r"(b1));
}
__device__ __forceinline__ void red4(float* p, float4 v) {
    asm volatile("red.global.add.v4.f32 [%0], {%1,%2,%3,%4};"
                 :: "l"(p), "f"(v.x), "f"(v.y), "f"(v.z), "f"(v.w) : "memory");
}

// ---------------- init ------------------------------------------------------
__global__ void init_kernel() {
    int i = blockIdx.x * blockDim.x + threadIdx.x;
    if (i < NUN * 256) g_agg_u[i] = 0.f;
    if (i < NVN * 256) g_agg_v[i] = 0.f;
    if (i < NUN) g_s_bwd[i] = 0.f;
    if (i < NVN) g_s_fwd[i] = 0.f;
}

// =====================  tf32 tensor-core GEMM (R3/R5-proven body)  ==========
// BM=64, 128 threads, warp tile 64 x (BN/4), mma.m16n8k8.tf32, KC=32,
// cvt once at smem store.
// MODE 0: plain                      MODE 2: relu
// MODE 3: relu(.. + g_pu[src[r]] + g_pv[dst[r]])
// MODE 4: relu, A row r scaled by 1/rowScale[r]
template <int BN, int KTOT, int MODE>
__launch_bounds__(128)
__global__ void tf32gemm(const float* __restrict__ A,
                         const float* __restrict__ W,
                         const float* __restrict__ bias,
                         float* __restrict__ C, int ldc, int col_off, int M,
                         const int* __restrict__ src, const int* __restrict__ dst,
                         const float* __restrict__ rowScale) {
    constexpr int KC = 32;
    constexpr int WN = BN / 4;
    constexpr int NT = WN / 8;
    constexpr int ASTR = KC + 4;          // 36 ≡ 4 (mod 32)
    constexpr int BSTR = BN + 8;          // ≡ 8 (mod 32)
    __shared__ float As[64 * ASTR];
    __shared__ float Bs[KC * BSTR];

    const int t    = threadIdx.x;
    const int warp = t >> 5;
    const int lane = t & 31;
    const int qr   = lane >> 2;
    const int qc   = lane & 3;
    const int row0 = blockIdx.x * 64;

    float acc[4][NT][4];
#pragma unroll
    for (int i = 0; i < 4; i++)
#pragma unroll
        for (int j = 0; j < NT; j++)
#pragma unroll
            for (int q = 0; q < 4; q++) acc[i][j][q] = 0.f;

    for (int k0 = 0; k0 < KTOT; k0 += KC) {
#pragma unroll
        for (int p = 0; p < 4; p++) {
            int slot = t + p * 128;
            int r = slot >> 3, c = slot & 7;
            float4 v = make_float4(0.f, 0.f, 0.f, 0.f);
            int gr = row0 + r;
            if (gr < M) {
                v = *(const float4*)&A[(size_t)gr * KTOT + k0 + c * 4];
                if (MODE == 4) {
                    float sden = rowScale[gr];
                    float rs = sden > 0.f ? __fdividef(1.f, sden) : 0.f;
                    v.x *= rs; v.y *= rs; v.z *= rs; v.w *= rs;
                }
            }
            float* s = &As[r * ASTR + c * 4];
            s[0] = f2tf32(v.x); s[1] = f2tf32(v.y);
            s[2] = f2tf32(v.z); s[3] = f2tf32(v.w);
        }
#pragma unroll
        for (int p = 0; p < KC * BN / 512; p++) {
            int slot = t + p * 128;
            int kr = slot / (BN / 4);
            int c  = slot % (BN / 4);
            float4 v = *(const float4*)&W[(size_t)(k0 + kr) * BN + c * 4];
            float* s = &Bs[kr * BSTR + c * 4];
            s[0] = f2tf32(v.x); s[1] = f2tf32(v.y);
            s[2] = f2tf32(v.z); s[3] = f2tf32(v.w);
        }
        __syncthreads();
#pragma unroll
        for (int kk = 0; kk < KC; kk += 8) {
            uint32_t a[4][4];
#pragma unroll
            for (int i = 0; i < 4; i++) {
                const float* base = &As[(16 * i + qr) * ASTR + kk + qc];
                a[i][0] = __float_as_uint(base[0]);
                a[i][1] = __float_as_uint(base[8 * ASTR]);
                a[i][2] = __float_as_uint(base[4]);
                a[i][3] = __float_as_uint(base[8 * ASTR + 4]);
            }
#pragma unroll
            for (int j = 0; j < NT; j++) {
                int n = warp * WN + j * 8 + qr;
                uint32_t b0 = __float_as_uint(Bs[(kk + qc) * BSTR + n]);
                uint32_t b1 = __float_as_uint(Bs[(kk + 4 + qc) * BSTR + n]);
#pragma unroll
                for (int i = 0; i < 4; i++) mma_tf32(acc[i][j], a[i], b0, b1);
            }
        }
        __syncthreads();
    }

#pragma unroll
    for (int i = 0; i < 4; i++) {
#pragma unroll
        for (int h = 0; h < 2; h++) {
            int gr = row0 + 16 * i + qr + 8 * h;
            if (gr >= M) continue;
            int s_ = 0, d_ = 0;
            if (MODE == 3) { s_ = src[gr]; d_ = dst[gr]; }
#pragma unroll
            for (int j = 0; j < NT; j++) {
                int col = warp * WN + j * 8 + 2 * qc;
                float x0 = acc[i][j][2 * h]     + bias[col];
                float x1 = acc[i][j][2 * h + 1] + bias[col + 1];
                if (MODE == 3) {
                    const float* pu = &g_pu[0] + (size_t)s_ * 256 + col;
                    const float* pv = &g_pv[0] + (size_t)d_ * 256 + col;
                    x0 += pu[0] + pv[0];
                    x1 += pu[1] + pv[1];
                }
                if (MODE >= 2) { x0 = fmaxf(x0, 0.f); x1 = fmaxf(x1, 0.f); }
                *(float2*)&C[(size_t)gr * ldc + col_off + col] = make_float2(x0, x1);
            }
        }
    }
}

// ---------------- fp32 SIMT GEMM (attention projections) --------------------
__launch_bounds__(128)
__global__ void gemm64_f32(const float* __restrict__ A, int K,
                           const float* __restrict__ W, int Ntot,
                           const float* __restrict__ bias,
                           float* __restrict__ C, int ldc, int M) {
    __shared__ __align__(16) float As[16][64];
    __shared__ __align__(16) float Ws[16][64];
    const int t  = threadIdx.x;
    const int ty = t >> 3;
    const int tx = t & 7;
    const int row0 = blockIdx.y * 64;
    const int n0   = blockIdx.x * 64;

    float acc[4][8];
#pragma unroll
    for (int i = 0; i < 4; i++)
#pragma unroll
        for (int j = 0; j < 8; j++) acc[i][j] = 0.f;

    for (int k0 = 0; k0 < K; k0 += 16) {
#pragma unroll
        for (int j = 0; j < 2; j++) {
            int idx = t * 2 + j;
            int r  = idx >> 2;
            int c4 = idx & 3;
            float4 v = make_float4(0.f, 0.f, 0.f, 0.f);
            int gr = row0 + r;
            if (gr < M) v = *(const float4*)&A[(size_t)gr * K + k0 + c4 * 4];
            As[c4 * 4 + 0][r] = v.x;
            As[c4 * 4 + 1][r] = v.y;
            As[c4 * 4 + 2][r] = v.z;
            As[c4 * 4 + 3][r] = v.w;
        }
#pragma unroll
        for (int j = 0; j < 2; j++) {
            int idx = t * 2 + j;
            int kr  = idx >> 4;
            int c4  = idx & 15;
            *(float4*)&Ws[kr][c4 * 4] =
                *(const float4*)&W[(size_t)(k0 + kr) * Ntot + n0 + c4 * 4];
        }
        __syncthreads();
#pragma unroll
        for (int kk = 0; kk < 16; kk++) {
            float4 a  = *(const float4*)&As[kk][ty * 4];
            float4 b0 = *(const float4*)&Ws[kk][tx * 8];
            float4 b1 = *(const float4*)&Ws[kk][tx * 8 + 4];
            float av[4] = {a.x, a.y, a.z, a.w};
            float bv[8] = {b0.x, b0.y, b0.z, b0.w, b1.x, b1.y, b1.z, b1.w};
#pragma unroll
            for (int i = 0; i < 4; i++)
#pragma unroll
                for (int j = 0; j < 8; j++) acc[i][j] = fmaf(av[i], bv[j], acc[i][j]);
        }
        __syncthreads();
    }

#pragma unroll
    for (int i = 0; i < 4; i++) {
        int r = row0 + ty * 4 + i;
        if (r >= M) continue;
#pragma unroll
        for (int j = 0; j < 8; j++) {
            int n = n0 + tx * 8 + j;
            C[(size_t)r * ldc + n] = acc[i][j] + bias[n];
        }
    }
}

// ===== fused edge pass: logit -> exp (no max shift; fp32-safe, |logit|<~50)
//       -> unnormalized weighted scatter + segment sums.  One pass over edges.
__global__ void edge_kernel(const float* __restrict__ e_feat,
                            const float* __restrict__ u_feat,
                            const float* __restrict__ v_feat,
                            const int* __restrict__ src,
                            const int* __restrict__ dst) {
    int e = blockIdx.x * 8 + (threadIdx.x >> 5);
    int lane = threadIdx.x & 31;
    int c = lane * 4;
    int s = src[e], d = dst[e];
    float4 ev = *(const float4*)&e_feat[(size_t)e * FIN + c];
    float4 uv = *(const float4*)&u_feat[(size_t)s * FIN + c];
    float4 vv = *(const float4*)&v_feat[(size_t)d * FIN + c];
    float4 au0 = *(const float4*)&g_att_u[(size_t)s * 256 + c];
    float4 au1 = *(const float4*)&g_att_u[(size_t)s * 256 + 128 + c];
    float4 av0 = *(const float4*)&g_att_v[(size_t)d * 256 + c];
    float4 av1 = *(const float4*)&g_att_v[(size_t)d * 256 + 128 + c];
    float sb = vv.x * au0.x + vv.y * au0.y + vv.z * au0.z + vv.w * au0.w
             + ev.x * au1.x + ev.y * au1.y + ev.z * au1.z + ev.w * au1.w;
    float sf = uv.x * av0.x + uv.y * av0.y + uv.z * av0.z + uv.w * av0.w
             + ev.x * av1.x + ev.y * av1.y + ev.z * av1.z + ev.w * av1.w;
#pragma unroll
    for (int o = 16; o; o >>= 1) {
        sb += __shfl_xor_sync(0xFFFFFFFFu, sb, o);
        sf += __shfl_xor_sync(0xFFFFFFFFu, sf, o);
    }
    float wb = expf(sb);
    float wf = expf(sf);
    float* agu = g_agg_u + (size_t)s * 256;
    float* agv = g_agg_v + (size_t)d * 256;
    red4(&agu[c],       make_float4(wb * vv.x, wb * vv.y, wb * vv.z, wb * vv.w));
    red4(&agu[c + 128], make_float4(wb * ev.x, wb * ev.y, wb * ev.z, wb * ev.w));
    red4(&agv[c],       make_float4(wf * uv.x, wf * uv.y, wf * uv.z, wf * uv.w));
    red4(&agv[c + 128], make_float4(wf * ev.x, wf * ev.y, wf * ev.z, wf * ev.w));
    if (lane == 0) {
        atomicAdd(&g_s_bwd[s], wb);
        atomicAdd(&g_s_fwd[d], wf);
    }
}

// ---------------- launch: forked-stream CUDA-graph DAG -----------------------
extern "C" void kernel_launch(void* const* d_in, const int* in_sizes, int n_in,
                              void* d_out, int out_size) {
    const float* e_feat = (const float*)d_in[0];
    const float* u_feat = (const float*)d_in[1];
    const float* v_feat = (const float*)d_in[2];
    const int*   src    = (const int*)d_in[3];
    const int*   dst    = (const int*)d_in[4];
    const float* We  = (const float*)d_in[5];  const float* be  = (const float*)d_in[6];
    const float* Wu  = (const float*)d_in[7];  const float* bu  = (const float*)d_in[8];
    const float* Wv  = (const float*)d_in[9];  const float* bv  = (const float*)d_in[10];
    const float* Wau = (const float*)d_in[11]; const float* bau = (const float*)d_in[12];
    const float* Wav = (const float*)d_in[13]; const float* bav = (const float*)d_in[14];
    const float* Wnu = (const float*)d_in[15]; const float* bnu = (const float*)d_in[16];
    const float* Wnv = (const float*)d_in[17]; const float* bnv = (const float*)d_in[18];
    const float* Vu  = (const float*)d_in[19]; const float* bVu = (const float*)d_in[20];
    const float* Vv  = (const float*)d_in[21]; const float* bVv = (const float*)d_in[22];

    float* out    = (float*)d_out;
    float* out_he = out;
    float* out_hu = out + (size_t)NEDGE * 256;
    float* out_hv = out_hu + (size_t)NUN * 256;

    float *pu, *pv, *au, *av, *aggu, *aggv, *sb, *sf;
    cudaGetSymbolAddress((void**)&pu,   g_pu);
    cudaGetSymbolAddress((void**)&pv,   g_pv);
    cudaGetSymbolAddress((void**)&au,   g_att_u);
    cudaGetSymbolAddress((void**)&av,   g_att_v);
    cudaGetSymbolAddress((void**)&aggu, g_agg_u);
    cudaGetSymbolAddress((void**)&aggv, g_agg_v);
    cudaGetSymbolAddress((void**)&sb,   g_s_bwd);
    cudaGetSymbolAddress((void**)&sf,   g_s_fwd);

    static cudaStream_t s1, s2, s3;
    static cudaEvent_t evRoot, evInit, evPu, evPv, evAgg, evSkip, evHv;
    static bool once = false;
    if (!once) {
        cudaStreamCreateWithFlags(&s1, cudaStreamNonBlocking);
        cudaStreamCreateWithFlags(&s2, cudaStreamNonBlocking);
        cudaStreamCreateWithFlags(&s3, cudaStreamNonBlocking);
        cudaEventCreateWithFlags(&evRoot, cudaEventDisableTiming);
        cudaEventCreateWithFlags(&evInit, cudaEventDisableTiming);
        cudaEventCreateWithFlags(&evPu,   cudaEventDisableTiming);
        cudaEventCreateWithFlags(&evPv,   cudaEventDisableTiming);
        cudaEventCreateWithFlags(&evAgg,  cudaEventDisableTiming);
        cudaEventCreateWithFlags(&evSkip, cudaEventDisableTiming);
        cudaEventCreateWithFlags(&evHv,   cudaEventDisableTiming);
        once = true;
    }

    const int MB = (NUN + 63) / 64;   // 157

    cudaEventRecord(evRoot, 0);

    // main: init scratch
    init_kernel<<<(NUN * 256 + 255) / 256, 256>>>();
    cudaEventRecord(evInit, 0);

    // s1: pu projection (feeds he epilogue)
    cudaStreamWaitEvent(s1, evRoot, 0);
    tf32gemm<256, 128, 0><<<MB, 128, 0, s1>>>(u_feat, Wu, bu, pu, 256, 0, NUN,
                                              nullptr, nullptr, nullptr);
    cudaEventRecord(evPu, s1);

    // s3: pv projection (parallel with pu), then skip halves
    cudaStreamWaitEvent(s3, evRoot, 0);
    tf32gemm<256, 128, 0><<<MB, 128, 0, s3>>>(v_feat, Wv, bv, pv, 256, 0, NVN,
                                              nullptr, nullptr, nullptr);
    cudaEventRecord(evPv, s3);
    tf32gemm<128, 128, 0><<<MB, 128, 0, s3>>>(u_feat, Vu, bVu, out_hu, 256, 0, NUN,
                                              nullptr, nullptr, nullptr);
    tf32gemm<128, 128, 0><<<MB, 128, 0, s3>>>(v_feat, Vv, bVv, out_hv, 256, 0, NVN,
                                              nullptr, nullptr, nullptr);
    cudaEventRecord(evSkip, s3);

    // s2: attention projections, fused edge pass, then head_v (same-stream order)
    cudaStreamWaitEvent(s2, evRoot, 0);
    gemm64_f32<<<dim3(4, MB), 128, 0, s2>>>(u_feat, 128, Wau, 256, bau, au, 256, NUN);
    gemm64_f32<<<dim3(4, MB), 128, 0, s2>>>(v_feat, 128, Wav, 256, bav, av, 256, NVN);
    cudaStreamWaitEvent(s2, evInit, 0);
    edge_kernel<<<NEDGE / 8, 256, 0, s2>>>(e_feat, u_feat, v_feat, src, dst);
    cudaEventRecord(evAgg, s2);
    tf32gemm<128, 256, 4><<<MB, 128, 0, s2>>>(aggv, Wnv, bnv, out_hv, 256, 128, NVN,
                                              nullptr, nullptr, sf);
    cudaEventRecord(evHv, s2);

    // main: he (waits pu AND pv), concurrent with the edge chain on s2
    cudaStreamWaitEvent(0, evPu, 0);
    cudaStreamWaitEvent(0, evPv, 0);
    tf32gemm<256, 128, 3><<<NEDGE / 64, 128>>>(e_feat, We, be, out_he, 256, 0,
                                               NEDGE, src, dst, nullptr);

    // main: head_u after aggregation; join all branches
    cudaStreamWaitEvent(0, evAgg, 0);
    tf32gemm<128, 256, 4><<<MB, 128>>>(aggu, Wnu, bnu, out_hu, 256, 128, NUN,
                                       nullptr, nullptr, sb);
    cudaStreamWaitEvent(0, evHv, 0);
    cudaStreamWaitEvent(0, evSkip, 0);
}

// round 13
// speedup vs baseline: 1.2441x; 1.0862x over previous
#include <cuda_runtime.h>
#include <math.h>
#include <stdint.h>

#define NEDGE 320000
#define NUN   10000
#define NVN   10000
#define FIN   128

// ---------------- scratch (static device globals; no allocation) ------------
__device__ float    g_pu[NUN * 256];
__device__ float    g_pv[NVN * 256];
__device__ float    g_att_u[NUN * 256];
__device__ float    g_att_v[NVN * 256];
__device__ float    g_agg_u[NUN * 256];   // UNNORMALIZED exp-weighted sums
__device__ float    g_agg_v[NVN * 256];
__device__ float    g_s_bwd[NUN];         // segment sums of exp
__device__ float    g_s_fwd[NVN];

__device__ __forceinline__ float f2tf32(float f) {
    uint32_t r;
    asm("cvt.rna.tf32.f32 %0, %1;" : "=r"(r) : "f"(f));
    return __uint_as_float(r);
}
__device__ __forceinline__ void mma_tf32(float* d, const uint32_t* a,
                                         uint32_t b0, uint32_t b1) {
    asm volatile(
        "mma.sync.aligned.m16n8k8.row.col.f32.tf32.tf32.f32 "
        "{%0,%1,%2,%3}, {%4,%5,%6,%7}, {%8,%9}, {%0,%1,%2,%3};"
        : "+f"(d[0]), "+f"(d[1]), "+f"(d[2]), "+f"(d[3])
        : "r"(a[0]), "r"(a[1]), "r"(a[2]), "r"(a[3]), "r"(b0), "r"(b1));
}
__device__ __forceinline__ void red4(float* p, float4 v) {
    asm volatile("red.global.add.v4.f32 [%0], {%1,%2,%3,%4};"
                 :: "l"(p), "f"(v.x), "f"(v.y), "f"(v.z), "f"(v.w) : "memory");
}

// ---------------- init ------------------------------------------------------
__global__ void init_kernel() {
    int i = blockIdx.x * blockDim.x + threadIdx.x;
    if (i < NUN * 256) g_agg_u[i] = 0.f;
    if (i < NVN * 256) g_agg_v[i] = 0.f;
    if (i < NUN) g_s_bwd[i] = 0.f;
    if (i < NVN) g_s_fwd[i] = 0.f;
}

// =====================  tf32 tensor-core GEMM (R3/R5-proven body)  ==========
// BM=64, 128 threads, warp tile 64 x (BN/4), mma.m16n8k8.tf32, KC=32,
// cvt once at smem store.
// MODE 0: plain                      MODE 2: relu
// MODE 3: relu(.. + g_pu[src[r]] + g_pv[dst[r]])
// MODE 4: relu, A row r scaled by 1/rowScale[r]
template <int BN, int KTOT, int MODE>
__launch_bounds__(128)
__global__ void tf32gemm(const float* __restrict__ A,
                         const float* __restrict__ W,
                         const float* __restrict__ bias,
                         float* __restrict__ C, int ldc, int col_off, int M,
                         const int* __restrict__ src, const int* __restrict__ dst,
                         const float* __restrict__ rowScale) {
    constexpr int KC = 32;
    constexpr int WN = BN / 4;
    constexpr int NT = WN / 8;
    constexpr int ASTR = KC + 4;          // 36 ≡ 4 (mod 32)
    constexpr int BSTR = BN + 8;          // ≡ 8 (mod 32)
    __shared__ float As[64 * ASTR];
    __shared__ float Bs[KC * BSTR];

    const int t    = threadIdx.x;
    const int warp = t >> 5;
    const int lane = t & 31;
    const int qr   = lane >> 2;
    const int qc   = lane & 3;
    const int row0 = blockIdx.x * 64;

    float acc[4][NT][4];
#pragma unroll
    for (int i = 0; i < 4; i++)
#pragma unroll
        for (int j = 0; j < NT; j++)
#pragma unroll
            for (int q = 0; q < 4; q++) acc[i][j][q] = 0.f;

    for (int k0 = 0; k0 < KTOT; k0 += KC) {
#pragma unroll
        for (int p = 0; p < 4; p++) {
            int slot = t + p * 128;
            int r = slot >> 3, c = slot & 7;
            float4 v = make_float4(0.f, 0.f, 0.f, 0.f);
            int gr = row0 + r;
            if (gr < M) {
                v = *(const float4*)&A[(size_t)gr * KTOT + k0 + c * 4];
                if (MODE == 4) {
                    float sden = rowScale[gr];
                    float rs = sden > 0.f ? __fdividef(1.f, sden) : 0.f;
                    v.x *= rs; v.y *= rs; v.z *= rs; v.w *= rs;
                }
            }
            float* s = &As[r * ASTR + c * 4];
            s[0] = f2tf32(v.x); s[1] = f2tf32(v.y);
            s[2] = f2tf32(v.z); s[3] = f2tf32(v.w);
        }
#pragma unroll
        for (int p = 0; p < KC * BN / 512; p++) {
            int slot = t + p * 128;
            int kr = slot / (BN / 4);
            int c  = slot % (BN / 4);
            float4 v = *(const float4*)&W[(size_t)(k0 + kr) * BN + c * 4];
            float* s = &Bs[kr * BSTR + c * 4];
            s[0] = f2tf32(v.x); s[1] = f2tf32(v.y);
            s[2] = f2tf32(v.z); s[3] = f2tf32(v.w);
        }
        __syncthreads();
#pragma unroll
        for (int kk = 0; kk < KC; kk += 8) {
            uint32_t a[4][4];
#pragma unroll
            for (int i = 0; i < 4; i++) {
                const float* base = &As[(16 * i + qr) * ASTR + kk + qc];
                a[i][0] = __float_as_uint(base[0]);
                a[i][1] = __float_as_uint(base[8 * ASTR]);
                a[i][2] = __float_as_uint(base[4]);
                a[i][3] = __float_as_uint(base[8 * ASTR + 4]);
            }
#pragma unroll
            for (int j = 0; j < NT; j++) {
                int n = warp * WN + j * 8 + qr;
                uint32_t b0 = __float_as_uint(Bs[(kk + qc) * BSTR + n]);
                uint32_t b1 = __float_as_uint(Bs[(kk + 4 + qc) * BSTR + n]);
#pragma unroll
                for (int i = 0; i < 4; i++) mma_tf32(acc[i][j], a[i], b0, b1);
            }
        }
        __syncthreads();
    }

#pragma unroll
    for (int i = 0; i < 4; i++) {
#pragma unroll
        for (int h = 0; h < 2; h++) {
            int gr = row0 + 16 * i + qr + 8 * h;
            if (gr >= M) continue;
            int s_ = 0, d_ = 0;
            if (MODE == 3) { s_ = src[gr]; d_ = dst[gr]; }
#pragma unroll
            for (int j = 0; j < NT; j++) {
                int col = warp * WN + j * 8 + 2 * qc;
                float x0 = acc[i][j][2 * h]     + bias[col];
                float x1 = acc[i][j][2 * h + 1] + bias[col + 1];
                if (MODE == 3) {
                    const float* pu = &g_pu[0] + (size_t)s_ * 256 + col;
                    const float* pv = &g_pv[0] + (size_t)d_ * 256 + col;
                    x0 += pu[0] + pv[0];
                    x1 += pu[1] + pv[1];
                }
                if (MODE >= 2) { x0 = fmaxf(x0, 0.f); x1 = fmaxf(x1, 0.f); }
                *(float2*)&C[(size_t)gr * ldc + col_off + col] = make_float2(x0, x1);
            }
        }
    }
}

// ===== fused edge pass: logit -> exp (no max shift; fp32-safe, |logit|<~50)
//       -> unnormalized weighted scatter + segment sums.  One pass over edges.
__global__ void edge_kernel(const float* __restrict__ e_feat,
                            const float* __restrict__ u_feat,
                            const float* __restrict__ v_feat,
                            const int* __restrict__ src,
                            const int* __restrict__ dst) {
    int e = blockIdx.x * 8 + (threadIdx.x >> 5);
    int lane = threadIdx.x & 31;
    int c = lane * 4;
    int s = src[e], d = dst[e];
    float4 ev = *(const float4*)&e_feat[(size_t)e * FIN + c];
    float4 uv = *(const float4*)&u_feat[(size_t)s * FIN + c];
    float4 vv = *(const float4*)&v_feat[(size_t)d * FIN + c];
    float4 au0 = *(const float4*)&g_att_u[(size_t)s * 256 + c];
    float4 au1 = *(const float4*)&g_att_u[(size_t)s * 256 + 128 + c];
    float4 av0 = *(const float4*)&g_att_v[(size_t)d * 256 + c];
    float4 av1 = *(const float4*)&g_att_v[(size_t)d * 256 + 128 + c];
    float sb = vv.x * au0.x + vv.y * au0.y + vv.z * au0.z + vv.w * au0.w
             + ev.x * au1.x + ev.y * au1.y + ev.z * au1.z + ev.w * au1.w;
    float sf = uv.x * av0.x + uv.y * av0.y + uv.z * av0.z + uv.w * av0.w
             + ev.x * av1.x + ev.y * av1.y + ev.z * av1.z + ev.w * av1.w;
#pragma unroll
    for (int o = 16; o; o >>= 1) {
        sb += __shfl_xor_sync(0xFFFFFFFFu, sb, o);
        sf += __shfl_xor_sync(0xFFFFFFFFu, sf, o);
    }
    float wb = __expf(sb);
    float wf = __expf(sf);
    float* agu = g_agg_u + (size_t)s * 256;
    float* agv = g_agg_v + (size_t)d * 256;
    red4(&agu[c],       make_float4(wb * vv.x, wb * vv.y, wb * vv.z, wb * vv.w));
    red4(&agu[c + 128], make_float4(wb * ev.x, wb * ev.y, wb * ev.z, wb * ev.w));
    red4(&agv[c],       make_float4(wf * uv.x, wf * uv.y, wf * uv.z, wf * uv.w));
    red4(&agv[c + 128], make_float4(wf * ev.x, wf * ev.y, wf * ev.z, wf * ev.w));
    if (lane == 0) {
        atomicAdd(&g_s_bwd[s], wb);
        atomicAdd(&g_s_fwd[d], wf);
    }
}

// ---------------- launch: 3-stream CUDA-graph DAG ----------------------------
extern "C" void kernel_launch(void* const* d_in, const int* in_sizes, int n_in,
                              void* d_out, int out_size) {
    const float* e_feat = (const float*)d_in[0];
    const float* u_feat = (const float*)d_in[1];
    const float* v_feat = (const float*)d_in[2];
    const int*   src    = (const int*)d_in[3];
    const int*   dst    = (const int*)d_in[4];
    const float* We  = (const float*)d_in[5];  const float* be  = (const float*)d_in[6];
    const float* Wu  = (const float*)d_in[7];  const float* bu  = (const float*)d_in[8];
    const float* Wv  = (const float*)d_in[9];  const float* bv  = (const float*)d_in[10];
    const float* Wau = (const float*)d_in[11]; const float* bau = (const float*)d_in[12];
    const float* Wav = (const float*)d_in[13]; const float* bav = (const float*)d_in[14];
    const float* Wnu = (const float*)d_in[15]; const float* bnu = (const float*)d_in[16];
    const float* Wnv = (const float*)d_in[17]; const float* bnv = (const float*)d_in[18];
    const float* Vu  = (const float*)d_in[19]; const float* bVu = (const float*)d_in[20];
    const float* Vv  = (const float*)d_in[21]; const float* bVv = (const float*)d_in[22];

    float* out    = (float*)d_out;
    float* out_he = out;
    float* out_hu = out + (size_t)NEDGE * 256;
    float* out_hv = out_hu + (size_t)NUN * 256;

    float *pu, *pv, *au, *av, *aggu, *aggv, *sb, *sf;
    cudaGetSymbolAddress((void**)&pu,   g_pu);
    cudaGetSymbolAddress((void**)&pv,   g_pv);
    cudaGetSymbolAddress((void**)&au,   g_att_u);
    cudaGetSymbolAddress((void**)&av,   g_att_v);
    cudaGetSymbolAddress((void**)&aggu, g_agg_u);
    cudaGetSymbolAddress((void**)&aggv, g_agg_v);
    cudaGetSymbolAddress((void**)&sb,   g_s_bwd);
    cudaGetSymbolAddress((void**)&sf,   g_s_fwd);

    static cudaStream_t s1, s2, s3;
    static cudaEvent_t evRoot, evInit, evPu, evPv, evAttV, evAgg, evSkip, evHv;
    static bool once = false;
    if (!once) {
        cudaStreamCreateWithFlags(&s1, cudaStreamNonBlocking);
        cudaStreamCreateWithFlags(&s2, cudaStreamNonBlocking);
        cudaStreamCreateWithFlags(&s3, cudaStreamNonBlocking);
        cudaEventCreateWithFlags(&evRoot, cudaEventDisableTiming);
        cudaEventCreateWithFlags(&evInit, cudaEventDisableTiming);
        cudaEventCreateWithFlags(&evPu,   cudaEventDisableTiming);
        cudaEventCreateWithFlags(&evPv,   cudaEventDisableTiming);
        cudaEventCreateWithFlags(&evAttV, cudaEventDisableTiming);
        cudaEventCreateWithFlags(&evAgg,  cudaEventDisableTiming);
        cudaEventCreateWithFlags(&evSkip, cudaEventDisableTiming);
        cudaEventCreateWithFlags(&evHv,   cudaEventDisableTiming);
        once = true;
    }

    const int MB = (NUN + 63) / 64;   // 157

    cudaEventRecord(evRoot, 0);

    // main: init scratch
    init_kernel<<<(NUN * 256 + 255) / 256, 256>>>();
    cudaEventRecord(evInit, 0);

    // s1: pu projection, then att_v (runs parallel with att_u on s2)
    cudaStreamWaitEvent(s1, evRoot, 0);
    tf32gemm<256, 128, 0><<<MB, 128, 0, s1>>>(u_feat, Wu, bu, pu, 256, 0, NUN,
                                              nullptr, nullptr, nullptr);
    cudaEventRecord(evPu, s1);
    tf32gemm<256, 128, 0><<<MB, 128, 0, s1>>>(v_feat, Wav, bav, av, 256, 0, NVN,
                                              nullptr, nullptr, nullptr);
    cudaEventRecord(evAttV, s1);

    // s3: pv projection (parallel with pu), then skip halves
    cudaStreamWaitEvent(s3, evRoot, 0);
    tf32gemm<256, 128, 0><<<MB, 128, 0, s3>>>(v_feat, Wv, bv, pv, 256, 0, NVN,
                                              nullptr, nullptr, nullptr);
    cudaEventRecord(evPv, s3);
    tf32gemm<128, 128, 0><<<MB, 128, 0, s3>>>(u_feat, Vu, bVu, out_hu, 256, 0, NUN,
                                              nullptr, nullptr, nullptr);
    tf32gemm<128, 128, 0><<<MB, 128, 0, s3>>>(v_feat, Vv, bVv, out_hv, 256, 0, NVN,
                                              nullptr, nullptr, nullptr);
    cudaEventRecord(evSkip, s3);

    // s2: att_u (tf32), fused edge pass (waits att_v + init), then head_v
    cudaStreamWaitEvent(s2, evRoot, 0);
    tf32gemm<256, 128, 0><<<MB, 128, 0, s2>>>(u_feat, Wau, bau, au, 256, 0, NUN,
                                              nullptr, nullptr, nullptr);
    cudaStreamWaitEvent(s2, evInit, 0);
    cudaStreamWaitEvent(s2, evAttV, 0);
    edge_kernel<<<NEDGE / 8, 256, 0, s2>>>(e_feat, u_feat, v_feat, src, dst);
    cudaEventRecord(evAgg, s2);
    tf32gemm<128, 256, 4><<<MB, 128, 0, s2>>>(aggv, Wnv, bnv, out_hv, 256, 128, NVN,
                                              nullptr, nullptr, sf);
    cudaEventRecord(evHv, s2);

    // main: he (waits pu AND pv), concurrent with the edge chain on s2
    cudaStreamWaitEvent(0, evPu, 0);
    cudaStreamWaitEvent(0, evPv, 0);
    tf32gemm<256, 128, 3><<<NEDGE / 64, 128>>>(e_feat, We, be, out_he, 256, 0,
                                               NEDGE, src, dst, nullptr);

    // main: head_u after aggregation; join all branches
    cudaStreamWaitEvent(0, evAgg, 0);
    tf32gemm<128, 256, 4><<<MB, 128>>>(aggu, Wnu, bnu, out_hu, 256, 128, NUN,
                                       nullptr, nullptr, sb);
    cudaStreamWaitEvent(0, evHv, 0);
    cudaStreamWaitEvent(0, evSkip, 0);
}